// round 10
// baseline (speedup 1.0000x reference)
#include <cuda_runtime.h>
#include <cstdint>

// Problem constants: x [8,4096,128] -> N=32768 rows, D=128; codebooks [4,1024,128]
#define RVQ_N   32768
#define RVQ_D   128
#define RVQ_K   1024
#define RVQ_M   4
#define ND_TOTAL (RVQ_N * RVQ_D)
#define NBLK    512            // level-kernel grid (64 rows per block)
#define ROWS_B  64             // rows per block
#define CTILE   128            // codes per tile
#define NTILES  (RVQ_K / CTILE)           // 8
#define KC      16                        // dims per k-chunk
#define NGCHUNK (NTILES * (RVQ_D / KC))   // 64
#define SRD     132            // stride (floats) of duplicated-row tile [128][SRD]
#define SKEY_STRIDE 17

// Scratch (device globals: allocation-free per harness rules)
static __device__ float  g_resid[ND_TOTAL];            // 16 MB residual buffer
static __device__ float  g_e2[RVQ_M * RVQ_K];          // per-code squared norms
static __device__ float  g_cbT[RVQ_M * RVQ_D * RVQ_K]; // codebooks transposed [lvl][d][k]
static __device__ double g_lsum[RVQ_M * NBLK];         // per-(level,block) loss partials

// ---- packed f32x2 helpers ----
__device__ __forceinline__ uint64_t pk2(float a, float b) {
    uint64_t r;
    asm("mov.b64 %0, {%1, %2};" : "=l"(r) : "f"(a), "f"(b));
    return r;
}
__device__ __forceinline__ void upk2(float& a, float& b, uint64_t v) {
    asm("mov.b64 {%0, %1}, %2;" : "=f"(a), "=f"(b) : "l"(v));
}
__device__ __forceinline__ void ffma2(uint64_t& acc, uint64_t a, uint64_t b) {
    asm("fma.rn.f32x2 %0, %1, %2, %0;" : "+l"(acc) : "l"(a), "l"(b));
}

// ---------------------------------------------------------------------------
// e2[k] = sum_d cb[k][d]^2
// ---------------------------------------------------------------------------
__global__ void rvq_e2_kernel(const float* __restrict__ cb) {
    int k = blockIdx.x * blockDim.x + threadIdx.x;
    if (k < RVQ_M * RVQ_K) {
        const float* c = cb + (size_t)k * RVQ_D;
        float s = 0.f;
        #pragma unroll 8
        for (int i = 0; i < RVQ_D; i++)
            s = __fadd_rn(s, __fmul_rn(c[i], c[i]));
        g_e2[k] = s;
    }
}

// ---------------------------------------------------------------------------
// Transpose codebooks: g_cbT[lvl][d][k] = cb[lvl][k][d]
// ---------------------------------------------------------------------------
__global__ void rvq_tr_kernel(const float* __restrict__ cb) {
    int i = blockIdx.x * blockDim.x + threadIdx.x;
    if (i < RVQ_M * RVQ_K * RVQ_D) {
        int lvl = i >> 17;
        int r   = i & ((1 << 17) - 1);
        int k   = r >> 7;
        int d   = r & 127;
        g_cbT[lvl * (RVQ_D * RVQ_K) + d * RVQ_K + k] = cb[i];
    }
}

// ---------------------------------------------------------------------------
// One RVQ level: packed-f32x2 GEMM, 4 rows x 8 codes per thread. All packed
// operands load directly from smem (rows pre-duplicated, codes paired) —
// the inner loop is 4 LDS.128 + 16 FFMA2 with ZERO packing MOVs.
// Numerics mirror the reference: dist = fl( fl(r2+e2) - 2*dot ), r2 = strict
// 128-element left-fold, argmin = first (lowest-index) min. f32x2 lanes round
// exactly like scalar FFMA in identical k-order -> dots bit-identical.
// ---------------------------------------------------------------------------
__global__ void __launch_bounds__(256, 2) rvq_level_v5(
    const float* __restrict__ x,
    const float* __restrict__ cb,
    float* __restrict__ y,
    int lvl)
{
    extern __shared__ unsigned char dynsmem[];
    float* s_rd = (float*)dynsmem;                        // [128 dims][SRD] duplicated rows
    float* s_c  = s_rd + 128 * SRD;                       // [2][KC][CTILE]
    float* sE2  = s_c + 2 * KC * CTILE;                   // [1024]
    float* sr2  = sE2 + RVQ_K;                            // [64]
    unsigned long long* skey = (unsigned long long*)(sr2 + 64);   // [64][SKEY_STRIDE]
    double* sredd = (double*)(skey + 64 * SKEY_STRIDE);   // [64]

    const int tid = threadIdx.x;
    const int tx  = tid & 15;      // code coord: 8 codes each -> 128
    const int ty  = tid >> 4;      // row coord:  4 rows each  -> 64
    const int row0 = blockIdx.x * ROWS_B;

    const float* __restrict__ cbl = cb + (size_t)lvl * RVQ_K * RVQ_D;
    const float* __restrict__ cbT = g_cbT + (size_t)lvl * RVQ_D * RVQ_K;
    const float* __restrict__ src = (lvl == 0) ? x : (const float*)g_resid;

    // ---- load residual tile, transposed + duplicated into smem ----
    {
        #pragma unroll
        for (int it = 0; it < 8; it++) {
            int idx = tid + (it << 8);             // 2048 float4s
            int row = idx >> 5, d4 = idx & 31;
            float4 v = ((const float4*)(src + (size_t)(row0 + row) * RVQ_D))[d4];
            uint64_t* p0 = (uint64_t*)(s_rd + (4 * d4 + 0) * SRD + 2 * row);
            uint64_t* p1 = (uint64_t*)(s_rd + (4 * d4 + 1) * SRD + 2 * row);
            uint64_t* p2 = (uint64_t*)(s_rd + (4 * d4 + 2) * SRD + 2 * row);
            uint64_t* p3 = (uint64_t*)(s_rd + (4 * d4 + 3) * SRD + 2 * row);
            *p0 = pk2(v.x, v.x);
            *p1 = pk2(v.y, v.y);
            *p2 = pk2(v.z, v.z);
            *p3 = pk2(v.w, v.w);
        }
    }
    // stage e2 for this level
    #pragma unroll
    for (int it = 0; it < 4; it++)
        sE2[tid + (it << 8)] = g_e2[lvl * RVQ_K + tid + (it << 8)];
    __syncthreads();

    // ---- r2: strict sequential left-fold over 128 dims (matches reference) ----
    if (tid < 64) {
        float p = 0.f;
        #pragma unroll 8
        for (int d = 0; d < 128; d++) {
            float v = s_rd[d * SRD + 2 * tid];
            p = __fadd_rn(p, __fmul_rn(v, v));
        }
        sr2[tid] = p;
    }
    __syncthreads();

    float r2v[4];
    #pragma unroll
    for (int i = 0; i < 4; i++) r2v[i] = sr2[4 * ty + i];

    unsigned long long bk[4];
    #pragma unroll
    for (int i = 0; i < 4; i++) bk[i] = ~0ull;

    uint64_t acc2[16];   // [i(row 0..3)][jp(code pair 0..3)]

    // ---- prefetch code chunk 0 (transposed codebook; coalesced) ----
    const int kl = tid >> 5;     // 0..7
    const int c4 = tid & 31;     // float4 column (32*4 = 128 codes)
    float4 pf0, pf1;
    {
        const float4* gp = (const float4*)(cbT + (size_t)kl * RVQ_K) + c4;
        pf0 = gp[0];
        pf1 = gp[8 * RVQ_K / 4];
    }

    // ---- main loop: 8 code tiles x 8 k-chunks, double-buffered, 1 sync/iter ----
    #pragma unroll 1
    for (int g = 0; g < NGCHUNK; g++) {
        float* sc = s_c + (g & 1) * (KC * CTILE);
        ((float4*)(sc + (kl    ) * CTILE))[c4] = pf0;
        ((float4*)(sc + (kl + 8) * CTILE))[c4] = pf1;

        if (g + 1 < NGCHUNK) {
            int t8 = (g + 1) >> 3, k8 = (g + 1) & 7;
            const float4* gp = (const float4*)(cbT + (size_t)(k8 * KC + kl) * RVQ_K
                                               + t8 * CTILE) + c4;
            pf0 = gp[0];
            pf1 = gp[8 * RVQ_K / 4];
        }
        __syncthreads();

        if ((g & 7) == 0) {
            #pragma unroll
            for (int i = 0; i < 16; i++) acc2[i] = 0ull;
        }

        const int kc16 = (g & 7) * KC;
        #pragma unroll 4
        for (int k = 0; k < KC; k++) {
            // rows: 4 broadcast pairs, loaded packed (no MOVs)
            const ulonglong2* rp =
                (const ulonglong2*)(s_rd + (kc16 + k) * SRD + 8 * ty);
            ulonglong2 rA = rp[0], rB = rp[1];
            // codes: 4 pairs of adjacent codes, loaded packed
            const ulonglong2* cp =
                (const ulonglong2*)(sc + k * CTILE + 8 * tx);
            ulonglong2 cA = cp[0], cB = cp[1];
            uint64_t rr[4] = {rA.x, rA.y, rB.x, rB.y};
            uint64_t cd[4] = {cA.x, cA.y, cB.x, cB.y};
            #pragma unroll
            for (int i = 0; i < 4; i++)
                #pragma unroll
                for (int jp = 0; jp < 4; jp++)
                    ffma2(acc2[i * 4 + jp], rr[i], cd[jp]);
        }

        if ((g & 7) == 7) {   // end of a code tile: fold into running argmin
            int tile = g >> 3;
            int cbase = tile * CTILE + 8 * tx;
            const float4* ep = (const float4*)(sE2 + cbase);
            float4 e0 = ep[0], e1 = ep[1];
            float ev[8] = {e0.x, e0.y, e0.z, e0.w, e1.x, e1.y, e1.z, e1.w};
            #pragma unroll
            for (int i = 0; i < 4; i++) {
                #pragma unroll
                for (int jp = 0; jp < 4; jp++) {
                    float d0, d1;
                    upk2(d0, d1, acc2[i * 4 + jp]);
                    float A0    = __fadd_rn(r2v[i], ev[2 * jp]);      // fl(r2+e2)
                    float dist0 = __fadd_rn(A0, -2.0f * d0);          // fl(A-2dot)
                    unsigned long long k0 =
                        ((unsigned long long)__float_as_uint(dist0) << 32) |
                        (unsigned)(cbase + 2 * jp);
                    if (k0 < bk[i]) bk[i] = k0;
                    float A1    = __fadd_rn(r2v[i], ev[2 * jp + 1]);
                    float dist1 = __fadd_rn(A1, -2.0f * d1);
                    unsigned long long k1 =
                        ((unsigned long long)__float_as_uint(dist1) << 32) |
                        (unsigned)(cbase + 2 * jp + 1);
                    if (k1 < bk[i]) bk[i] = k1;
                }
            }
        }
    }
    __syncthreads();

    // ---- cross-thread argmin per row (16 tx threads per row) ----
    #pragma unroll
    for (int i = 0; i < 4; i++) skey[(4 * ty + i) * SKEY_STRIDE + tx] = bk[i];
    __syncthreads();
    if (tid < 64) {
        unsigned long long b = skey[tid * SKEY_STRIDE];
        #pragma unroll
        for (int t = 1; t < 16; t++) {
            unsigned long long k2 = skey[tid * SKEY_STRIDE + t];
            if (k2 < b) b = k2;
        }
        skey[tid * SKEY_STRIDE] = b;
    }
    __syncthreads();

    // ---- epilogue: residual update, y accumulate, fp64 loss partial ----
    double ls = 0.0;
    if (tid < 64) {
        int row = tid, gr = row0 + row;
        int idx = (int)(skey[row * SKEY_STRIDE] & 0xffffffffull);
        const float4* q4 = (const float4*)(cbl + (size_t)idx * RVQ_D);
        float4* rout = (float4*)(g_resid + (size_t)gr * RVQ_D);
        float4* yp   = (float4*)(y + (size_t)gr * RVQ_D);
        #pragma unroll 4
        for (int d4 = 0; d4 < 32; d4++) {
            float4 q = q4[d4];
            float v0 = s_rd[(4 * d4 + 0) * SRD + 2 * row];
            float v1 = s_rd[(4 * d4 + 1) * SRD + 2 * row];
            float v2 = s_rd[(4 * d4 + 2) * SRD + 2 * row];
            float v3 = s_rd[(4 * d4 + 3) * SRD + 2 * row];
            float4 nr;
            nr.x = __fadd_rn(v0, -q.x);
            nr.y = __fadd_rn(v1, -q.y);
            nr.z = __fadd_rn(v2, -q.z);
            nr.w = __fadd_rn(v3, -q.w);
            rout[d4] = nr;
            ls = fma((double)nr.x, (double)nr.x, ls);
            ls = fma((double)nr.y, (double)nr.y, ls);
            ls = fma((double)nr.z, (double)nr.z, ls);
            ls = fma((double)nr.w, (double)nr.w, ls);
            float4 yv;
            if (lvl == 0) {
                yv = q;
            } else {
                yv = yp[d4];
                yv.x = __fadd_rn(yv.x, q.x);
                yv.y = __fadd_rn(yv.y, q.y);
                yv.z = __fadd_rn(yv.z, q.z);
                yv.w = __fadd_rn(yv.w, q.w);
            }
            yp[d4] = yv;
        }
    }
    if (tid < 64) sredd[tid] = ls;
    __syncthreads();
    #pragma unroll
    for (int s2 = 32; s2 > 0; s2 >>= 1) {
        if (tid < s2) sredd[tid] += sredd[tid + s2];
        __syncthreads();
    }
    if (tid == 0) g_lsum[lvl * NBLK + blockIdx.x] = sredd[0];
}

// ---------------------------------------------------------------------------
// total_loss = 1.25 * (sum of level residual^2 sums) / (N*D)
// ---------------------------------------------------------------------------
__global__ void rvq_finalize_kernel(float* __restrict__ out) {
    __shared__ double sred[256];
    int tid = threadIdx.x;
    double s = 0.0;
    #pragma unroll
    for (int i = 0; i < 8; i++) s += g_lsum[tid + i * 256];
    sred[tid] = s;
    __syncthreads();
    #pragma unroll
    for (int s2 = 128; s2 > 0; s2 >>= 1) {
        if (tid < s2) sred[tid] += sred[tid + s2];
        __syncthreads();
    }
    if (tid == 0) out[ND_TOTAL] = (float)(1.25 * sred[0] / (double)ND_TOTAL);
}

// ---------------------------------------------------------------------------
#define LEVEL_SMEM_BYTES ((128 * SRD + 2 * KC * CTILE + RVQ_K + 64) * 4 \
                          + 64 * SKEY_STRIDE * 8 + 64 * 8)

extern "C" void kernel_launch(void* const* d_in, const int* in_sizes, int n_in,
                              void* d_out, int out_size) {
    const float* x  = (const float*)d_in[0];   // [8,4096,128] fp32
    const float* cb = (const float*)d_in[1];   // [4,1024,128] fp32
    float* out = (float*)d_out;                // [N*D] y then [1] loss

    cudaFuncSetAttribute(rvq_level_v5,
                         cudaFuncAttributeMaxDynamicSharedMemorySize,
                         LEVEL_SMEM_BYTES);

    rvq_e2_kernel<<<(RVQ_M * RVQ_K + 255) / 256, 256>>>(cb);
    rvq_tr_kernel<<<(RVQ_M * RVQ_K * RVQ_D + 255) / 256, 256>>>(cb);
    for (int lvl = 0; lvl < RVQ_M; lvl++)
        rvq_level_v5<<<NBLK, 256, LEVEL_SMEM_BYTES>>>(x, cb, out, lvl);
    rvq_finalize_kernel<<<1, 256>>>(out);
    (void)in_sizes; (void)n_in; (void)out_size;
}

// round 15
// speedup vs baseline: 3.2264x; 3.2264x over previous
#include <cuda_runtime.h>
#include <cuda_fp16.h>
#include <cstdint>

// Problem constants: x [8,4096,128] -> N=32768 rows, D=128; codebooks [4,1024,128]
#define RVQ_N   32768
#define RVQ_D   128
#define RVQ_K   1024
#define RVQ_M   4
#define ND_TOTAL (RVQ_N * RVQ_D)
#define NBLK1   256            // approx kernel: 128 rows per CTA
#define NBLK2   (RVQ_N / 8)    // exact kernel: 8 rows (warps) per CTA -> 4096
#define CAND_CAP 192
#define MARGIN  6.0e-4f        // candidate margin on approx score (err sigma ~2e-5)

// Scratch (device globals: allocation-free per harness rules)
static __device__ float   g_resid[ND_TOTAL];             // 16 MB residual
static __device__ float   g_e2[RVQ_M * RVQ_K];           // exact code norms^2
static __device__ __half2 g_cbTh[RVQ_M * 64 * RVQ_K];    // fp16 codebook*1024, [lvl][d2][k]
static __device__ __half  g_s[(size_t)RVQ_N * RVQ_K];    // approx scores, 64 MB
static __device__ double  g_lsum[RVQ_M * NBLK2];         // loss partials

__device__ __forceinline__ unsigned h2u(__half2 h) {
    union { __half2 h; unsigned u; } c; c.h = h; return c.u;
}
__device__ __forceinline__ __half2 u2h(unsigned u) {
    union { unsigned u; __half2 h; } c; c.u = u; return c.h;
}

// ---------------------------------------------------------------------------
// e2[k] = sum_d cb[k][d]^2  (exact fp32)
// ---------------------------------------------------------------------------
__global__ void rvq_e2_kernel(const float* __restrict__ cb) {
    int k = blockIdx.x * blockDim.x + threadIdx.x;
    if (k < RVQ_M * RVQ_K) {
        const float* c = cb + (size_t)k * RVQ_D;
        float s = 0.f;
        #pragma unroll 8
        for (int i = 0; i < RVQ_D; i++)
            s = __fadd_rn(s, __fmul_rn(c[i], c[i]));
        g_e2[k] = s;
    }
}

// ---------------------------------------------------------------------------
// Pack codebook -> fp16, transposed [lvl][d2][k], scaled by 1024 (exact pow2)
// ---------------------------------------------------------------------------
__global__ void rvq_cbpack_kernel(const float* __restrict__ cb) {
    int i = blockIdx.x * blockDim.x + threadIdx.x;     // [lvl][d2][k]
    if (i < RVQ_M * 64 * RVQ_K) {
        int lvl = i >> 16;
        int r   = i & 65535;
        int d2  = r >> 10;
        int k   = r & 1023;
        float2 v = ((const float2*)cb)[((size_t)lvl * RVQ_K + k) * 64 + d2];
        g_cbTh[i] = __floats2half2_rn(v.x * 1024.f, v.y * 1024.f);
    }
}

// ---------------------------------------------------------------------------
// Pass 1: approximate scores via HFMA2 (2 MAC/instr). 128 rows x 1024 codes
// per CTA; per thread 8 rows x 8 codes; d paired into half2 lanes.
// Writes s~ = e2_k - 2*dot~ (fp16) to g_s for every (row, code).
// ---------------------------------------------------------------------------
__global__ void __launch_bounds__(256, 2) rvq_approx(
    const float* __restrict__ x, int lvl)
{
    __shared__ __half2 s_a[64 * 132];      // [d2][row] residual fp16 pairs
    __shared__ __half2 s_b[2][8 * 128];    // [buf][d2-local][code]

    const int tid = threadIdx.x;
    const int tx  = tid & 15;              // 8 codes each -> 128
    const int ty  = tid >> 4;              // 8 rows each  -> 128
    const int row0 = blockIdx.x * 128;

    const float* __restrict__ src = (lvl == 0) ? x : (const float*)g_resid;
    const __half2* __restrict__ cbp = g_cbTh + (size_t)lvl * 64 * RVQ_K;

    // ---- convert residual tile to fp16 pairs, transposed ----
    #pragma unroll
    for (int it = 0; it < 32; it++) {
        int idx = tid + (it << 8);
        int row = idx >> 6, d2 = idx & 63;
        float2 v = ((const float2*)(src + (size_t)(row0 + row) * RVQ_D))[d2];
        s_a[d2 * 132 + row] = __floats2half2_rn(v.x, v.y);
    }

    __half2 acc[64];
    __half2 pf[4];
    #pragma unroll
    for (int j = 0; j < 4; j++) {          // prefetch chunk g=0 (tile 0, ch 0)
        int i = tid + (j << 8);
        pf[j] = cbp[(size_t)(i >> 7) * RVQ_K + (i & 127)];
    }
    __syncthreads();

    #pragma unroll 1
    for (int g = 0; g < 64; g++) {         // 8 code tiles x 8 d2-chunks
        __half2* sb = s_b[g & 1];
        #pragma unroll
        for (int j = 0; j < 4; j++) {
            int i = tid + (j << 8);
            sb[(i >> 7) * 128 + (i & 127)] = pf[j];
        }
        if (g + 1 < 64) {
            int t = (g + 1) >> 3, ch = (g + 1) & 7;
            #pragma unroll
            for (int j = 0; j < 4; j++) {
                int i = tid + (j << 8);
                pf[j] = cbp[(size_t)(ch * 8 + (i >> 7)) * RVQ_K + t * 128 + (i & 127)];
            }
        }
        __syncthreads();

        if ((g & 7) == 0) {
            #pragma unroll
            for (int i = 0; i < 64; i++) acc[i] = __float2half2_rn(0.f);
        }

        const int chb = (g & 7) * 8;
        #pragma unroll
        for (int k2 = 0; k2 < 8; k2++) {
            const __half2* ra = s_a + (chb + k2) * 132 + 8 * ty;
            uint4 ua0 = *(const uint4*)(ra);
            uint4 ua1 = *(const uint4*)(ra + 4);
            const __half2* ca = sb + k2 * 128 + 8 * tx;
            uint4 uc0 = *(const uint4*)(ca);
            uint4 uc1 = *(const uint4*)(ca + 4);
            __half2 rr[8], cc[8];
            rr[0] = u2h(ua0.x); rr[1] = u2h(ua0.y); rr[2] = u2h(ua0.z); rr[3] = u2h(ua0.w);
            rr[4] = u2h(ua1.x); rr[5] = u2h(ua1.y); rr[6] = u2h(ua1.z); rr[7] = u2h(ua1.w);
            cc[0] = u2h(uc0.x); cc[1] = u2h(uc0.y); cc[2] = u2h(uc0.z); cc[3] = u2h(uc0.w);
            cc[4] = u2h(uc1.x); cc[5] = u2h(uc1.y); cc[6] = u2h(uc1.z); cc[7] = u2h(uc1.w);
            #pragma unroll
            for (int i = 0; i < 8; i++)
                #pragma unroll
                for (int j = 0; j < 8; j++)
                    acc[i * 8 + j] = __hfma2(rr[i], cc[j], acc[i * 8 + j]);
        }

        if ((g & 7) == 7) {                // tile done: emit s~ for 8x8 block
            int t = g >> 3;
            int cbase = t * 128 + 8 * tx;
            float4 e0 = *(const float4*)(g_e2 + lvl * RVQ_K + cbase);
            float4 e1 = *(const float4*)(g_e2 + lvl * RVQ_K + cbase + 4);
            float ev[8] = {e0.x, e0.y, e0.z, e0.w, e1.x, e1.y, e1.z, e1.w};
            #pragma unroll
            for (int i = 0; i < 8; i++) {
                __half hs[8];
                #pragma unroll
                for (int j = 0; j < 8; j++) {
                    __half2 a = acc[i * 8 + j];
                    float dp = __fadd_rn(__low2float(a), __high2float(a))
                               * 9.765625e-04f;              // exact /1024
                    hs[j] = __float2half_rn(__fmaf_rn(-2.f, dp, ev[j]));
                }
                uint4 st;
                st.x = h2u(__halves2half2(hs[0], hs[1]));
                st.y = h2u(__halves2half2(hs[2], hs[3]));
                st.z = h2u(__halves2half2(hs[4], hs[5]));
                st.w = h2u(__halves2half2(hs[6], hs[7]));
                *(uint4*)(g_s + (size_t)(row0 + 8 * ty + i) * RVQ_K + cbase) = st;
            }
        }
    }
}

// ---------------------------------------------------------------------------
// Pass 2: warp-per-row. Scan s~, select candidates within MARGIN of approx
// min, rescore exactly with the validated reference numerics, update
// residual / y / loss.
// ---------------------------------------------------------------------------
__global__ void __launch_bounds__(256) rvq_exact(
    const float* __restrict__ x,
    const float* __restrict__ cb,
    float* __restrict__ y,
    int lvl)
{
    __shared__ int    s_cnt[8];
    __shared__ int    s_list[8][CAND_CAP];
    __shared__ double sredd[8];

    const int tid  = threadIdx.x;
    const int w    = tid >> 5;
    const int lane = tid & 31;
    const int row  = blockIdx.x * 8 + w;

    const float* __restrict__ cbl = cb + (size_t)lvl * RVQ_K * RVQ_D;
    const float* __restrict__ src = (lvl == 0) ? x : (const float*)g_resid;

    // row data: lane holds dims 4L..4L+3
    float4 rv = ((const float4*)(src + (size_t)row * RVQ_D))[lane];

    // r2: strict sequential left-fold over 128 dims (reference semantics)
    float r2 = 0.f;
    #pragma unroll 8
    for (int L = 0; L < 32; L++) {
        float a0 = __shfl_sync(0xffffffffu, rv.x, L);
        float a1 = __shfl_sync(0xffffffffu, rv.y, L);
        float a2 = __shfl_sync(0xffffffffu, rv.z, L);
        float a3 = __shfl_sync(0xffffffffu, rv.w, L);
        r2 = __fadd_rn(r2, __fmul_rn(a0, a0));
        r2 = __fadd_rn(r2, __fmul_rn(a1, a1));
        r2 = __fadd_rn(r2, __fmul_rn(a2, a2));
        r2 = __fadd_rn(r2, __fmul_rn(a3, a3));
    }

    // scan s~ row: lane covers codes 256*i + 8*lane .. +7
    const uint4* sp = (const uint4*)(g_s + (size_t)row * RVQ_K);
    uint4 su[4];
    float gmin[4];
    float m = 3.4e38f;
    #pragma unroll
    for (int i = 0; i < 4; i++) {
        su[i] = __ldg(&sp[32 * i + lane]);
        float2 f0 = __half22float2(u2h(su[i].x));
        float2 f1 = __half22float2(u2h(su[i].y));
        float2 f2 = __half22float2(u2h(su[i].z));
        float2 f3 = __half22float2(u2h(su[i].w));
        float mm = fminf(fminf(fminf(f0.x, f0.y), fminf(f1.x, f1.y)),
                         fminf(fminf(f2.x, f2.y), fminf(f3.x, f3.y)));
        gmin[i] = mm;
        m = fminf(m, mm);
    }
    #pragma unroll
    for (int off = 16; off > 0; off >>= 1)
        m = fminf(m, __shfl_xor_sync(0xffffffffu, m, off));
    const float thr = m + MARGIN;

    if (lane == 0) s_cnt[w] = 0;
    __syncwarp();
    #pragma unroll
    for (int i = 0; i < 4; i++) {
        if (gmin[i] <= thr) {
            float f[8];
            float2 f0 = __half22float2(u2h(su[i].x));
            float2 f1 = __half22float2(u2h(su[i].y));
            float2 f2 = __half22float2(u2h(su[i].z));
            float2 f3 = __half22float2(u2h(su[i].w));
            f[0] = f0.x; f[1] = f0.y; f[2] = f1.x; f[3] = f1.y;
            f[4] = f2.x; f[5] = f2.y; f[6] = f3.x; f[7] = f3.y;
            #pragma unroll
            for (int j = 0; j < 8; j++) {
                if (f[j] <= thr) {
                    int pos = atomicAdd(&s_cnt[w], 1);
                    if (pos < CAND_CAP)
                        s_list[w][pos] = 256 * i + 8 * lane + j;
                }
            }
        }
    }
    __syncwarp();
    int cnt = s_cnt[w];
    if (cnt > CAND_CAP) cnt = CAND_CAP;

    // exact rescore of candidates (reference dist semantics; packed-key ties)
    unsigned long long best = ~0ull;
    for (int c = 0; c < cnt; c++) {
        int k = s_list[w][c];
        float4 cv = __ldg(((const float4*)(cbl + (size_t)k * RVQ_D)) + lane);
        float p = __fmaf_rn(rv.x, cv.x,
                  __fmaf_rn(rv.y, cv.y,
                  __fmaf_rn(rv.z, cv.z, __fmul_rn(rv.w, cv.w))));
        #pragma unroll
        for (int off = 16; off > 0; off >>= 1)
            p = __fadd_rn(p, __shfl_xor_sync(0xffffffffu, p, off));
        float e2k  = __ldg(&g_e2[lvl * RVQ_K + k]);
        float A    = __fadd_rn(r2, e2k);          // fl(r2 + e2)
        float dist = __fadd_rn(A, -2.0f * p);     // fl(A - 2*dot)
        unsigned long long key =
            ((unsigned long long)__float_as_uint(dist) << 32) | (unsigned)k;
        if (key < best) best = key;
    }

    // winner: residual update, y accumulate, fp64 loss (validated epilogue)
    int idx = (int)(best & 0xffffffffull);
    float4 q = __ldg(((const float4*)(cbl + (size_t)idx * RVQ_D)) + lane);
    float4 nr;
    nr.x = __fadd_rn(rv.x, -q.x);
    nr.y = __fadd_rn(rv.y, -q.y);
    nr.z = __fadd_rn(rv.z, -q.z);
    nr.w = __fadd_rn(rv.w, -q.w);
    ((float4*)(g_resid + (size_t)row * RVQ_D))[lane] = nr;

    double ls = 0.0;
    ls = fma((double)nr.x, (double)nr.x, ls);
    ls = fma((double)nr.y, (double)nr.y, ls);
    ls = fma((double)nr.z, (double)nr.z, ls);
    ls = fma((double)nr.w, (double)nr.w, ls);

    float4* yp = ((float4*)(y + (size_t)row * RVQ_D)) + lane;
    float4 yv;
    if (lvl == 0) {
        yv = q;
    } else {
        yv = *yp;
        yv.x = __fadd_rn(yv.x, q.x);
        yv.y = __fadd_rn(yv.y, q.y);
        yv.z = __fadd_rn(yv.z, q.z);
        yv.w = __fadd_rn(yv.w, q.w);
    }
    *yp = yv;

    #pragma unroll
    for (int off = 16; off > 0; off >>= 1)
        ls += __shfl_xor_sync(0xffffffffu, ls, off);
    if (lane == 0) sredd[w] = ls;
    __syncthreads();
    if (tid == 0) {
        double s = 0.0;
        #pragma unroll
        for (int i = 0; i < 8; i++) s += sredd[i];
        g_lsum[lvl * NBLK2 + blockIdx.x] = s;
    }
}

// ---------------------------------------------------------------------------
// total_loss = 1.25 * (sum of level residual^2 sums) / (N*D)
// ---------------------------------------------------------------------------
__global__ void rvq_finalize_kernel(float* __restrict__ out) {
    __shared__ double sred[256];
    int tid = threadIdx.x;
    double s = 0.0;
    #pragma unroll
    for (int i = 0; i < (RVQ_M * NBLK2) / 256; i++)
        s += g_lsum[tid + (i << 8)];
    sred[tid] = s;
    __syncthreads();
    #pragma unroll
    for (int s2 = 128; s2 > 0; s2 >>= 1) {
        if (tid < s2) sred[tid] += sred[tid + s2];
        __syncthreads();
    }
    if (tid == 0) out[ND_TOTAL] = (float)(1.25 * sred[0] / (double)ND_TOTAL);
}

// ---------------------------------------------------------------------------
extern "C" void kernel_launch(void* const* d_in, const int* in_sizes, int n_in,
                              void* d_out, int out_size) {
    const float* x  = (const float*)d_in[0];   // [8,4096,128] fp32
    const float* cb = (const float*)d_in[1];   // [4,1024,128] fp32
    float* out = (float*)d_out;                // [N*D] y then [1] loss

    rvq_e2_kernel<<<(RVQ_M * RVQ_K + 255) / 256, 256>>>(cb);
    rvq_cbpack_kernel<<<(RVQ_M * 64 * RVQ_K + 255) / 256, 256>>>(cb);
    for (int lvl = 0; lvl < RVQ_M; lvl++) {
        rvq_approx<<<NBLK1, 256>>>(x, lvl);
        rvq_exact<<<NBLK2, 256>>>(x, cb, out, lvl);
    }
    rvq_finalize_kernel<<<1, 256>>>(out);
    (void)in_sizes; (void)n_in; (void)out_size;
}